// round 4
// baseline (speedup 1.0000x reference)
#include <cuda_runtime.h>
#include <math.h>

#define BATCH 4
#define SEQ   4096
#define EMB   1024
#define HD    128
#define MTOT  (BATCH * SEQ)

// Scratch for projected q, k, v  (allocation-free: device globals)
__device__ float g_q[(size_t)MTOT * HD];
__device__ float g_k[(size_t)MTOT * HD];
__device__ float g_v[(size_t)MTOT * HD];

// ---------------------------------------------------------------------------
// Kernel 1: QKV projection. out[which] = x[M,E] @ W[E,H]
// Tile: 64 (M) x 128 (H full), BK=16. 256 threads, 4x8 register tile each.
// ---------------------------------------------------------------------------
__global__ __launch_bounds__(256) void qkv_kernel(
    const float* __restrict__ x,
    const float* __restrict__ Wq,
    const float* __restrict__ Wk,
    const float* __restrict__ Wv)
{
    const int which = blockIdx.y;
    const float* __restrict__ W = (which == 0) ? Wq : (which == 1) ? Wk : Wv;
    float* __restrict__ out = (which == 0) ? g_q : (which == 1) ? g_k : g_v;

    const int row_base = blockIdx.x * 64;

    __shared__ float xs[64][17];        // 64 x 16 (+1 pad)
    __shared__ float ws[16][132];       // 16 x 128 (+4 pad)

    const int tid = threadIdx.x;
    const int tx = tid & 15;            // 16 col-groups of 8
    const int ty = tid >> 4;            // 16 row-groups of 4
    const int c0 = tx * 8;
    const int r0 = ty * 4;

    float acc[4][8];
#pragma unroll
    for (int i = 0; i < 4; i++)
#pragma unroll
        for (int j = 0; j < 8; j++) acc[i][j] = 0.f;

    for (int k0 = 0; k0 < EMB; k0 += 16) {
        // x tile: 64x16 = 256 float4
        {
            int r = tid >> 2;
            int c = (tid & 3) * 4;
            float4 v = *(const float4*)&x[(size_t)(row_base + r) * EMB + k0 + c];
            xs[r][c + 0] = v.x; xs[r][c + 1] = v.y;
            xs[r][c + 2] = v.z; xs[r][c + 3] = v.w;
        }
        // W tile: 16x128 = 512 float4
#pragma unroll
        for (int it = 0; it < 2; it++) {
            int idx = tid + it * 256;
            int r = idx >> 5;
            int c = (idx & 31) * 4;
            float4 v = *(const float4*)&W[(size_t)(k0 + r) * HD + c];
            ws[r][c + 0] = v.x; ws[r][c + 1] = v.y;
            ws[r][c + 2] = v.z; ws[r][c + 3] = v.w;
        }
        __syncthreads();

#pragma unroll
        for (int kk = 0; kk < 16; kk++) {
            float a[4], b[8];
#pragma unroll
            for (int i = 0; i < 4; i++) a[i] = xs[r0 + i][kk];
#pragma unroll
            for (int j = 0; j < 8; j++) b[j] = ws[kk][c0 + j];
#pragma unroll
            for (int i = 0; i < 4; i++)
#pragma unroll
                for (int j = 0; j < 8; j++)
                    acc[i][j] = fmaf(a[i], b[j], acc[i][j]);
        }
        __syncthreads();
    }

#pragma unroll
    for (int i = 0; i < 4; i++) {
#pragma unroll
        for (int j = 0; j < 8; j += 4) {
            float4 v = make_float4(acc[i][j], acc[i][j + 1], acc[i][j + 2], acc[i][j + 3]);
            *(float4*)&out[(size_t)(row_base + r0 + i) * HD + c0 + j] = v;
        }
    }
}

// ---------------------------------------------------------------------------
// Kernel 2: causal flash attention.
// One CTA per (batch, 64-query tile). Iterates only causal K-tiles.
// smem: Q/K/V 64x128 (stride 132), P 64x64 (stride 68), row stats.
// ---------------------------------------------------------------------------
#define QSTR 132
#define PSTR 68
#define ATTN_SMEM_FLOATS (3 * 64 * QSTR + 64 * PSTR + 3 * 64)
#define ATTN_SMEM_BYTES  (ATTN_SMEM_FLOATS * 4)

__global__ __launch_bounds__(256) void attn_kernel(float* __restrict__ out)
{
    const int batch = blockIdx.y;
    const int qt = (int)(gridDim.x - 1) - (int)blockIdx.x;   // heavy tiles first
    const int q_base = qt * 64;
    const size_t boff = (size_t)batch * SEQ * HD;

    extern __shared__ float sm[];
    float* Qs  = sm;                        // 64 x 132
    float* Ks  = Qs + 64 * QSTR;            // 64 x 132
    float* Vs  = Ks + 64 * QSTR;            // 64 x 132
    float* Ps  = Vs + 64 * QSTR;            // 64 x 68
    float* m_s = Ps + 64 * PSTR;            // 64
    float* l_s = m_s + 64;                  // 64
    float* c_s = l_s + 64;                  // 64

    const int tid = threadIdx.x;

    // Load Q tile (64x128 = 2048 float4; 8 per thread)
    for (int idx = tid; idx < 64 * 32; idx += 256) {
        int r = idx >> 5;
        int c = (idx & 31) * 4;
        float4 v = *(const float4*)&g_q[boff + (size_t)(q_base + r) * HD + c];
        Qs[r * QSTR + c]     = v.x; Qs[r * QSTR + c + 1] = v.y;
        Qs[r * QSTR + c + 2] = v.z; Qs[r * QSTR + c + 3] = v.w;
    }
    if (tid < 64) { m_s[tid] = -1e30f; l_s[tid] = 0.f; }

    // thread tiles: S-GEMM 16x16 grid of 4x4; PV 16x16 grid of 4(rows)x8(hcols)
    const int sx = tid & 15, sy = tid >> 4;
    const int sc0 = sx * 4, sr0 = sy * 4;
    const int vh0 = sx * 8, vr0 = sy * 4;

    float o[4][8];
#pragma unroll
    for (int i = 0; i < 4; i++)
#pragma unroll
        for (int j = 0; j < 8; j++) o[i][j] = 0.f;

    const float scale = rsqrtf((float)HD);

    for (int kt = 0; kt <= qt; kt++) {
        __syncthreads();   // previous iter's Ps/Vs reads done; Q load visible on iter 0

        // Load K,V tiles
        const int k_base = kt * 64;
        for (int idx = tid; idx < 64 * 32; idx += 256) {
            int r = idx >> 5;
            int c = (idx & 31) * 4;
            float4 kv = *(const float4*)&g_k[boff + (size_t)(k_base + r) * HD + c];
            Ks[r * QSTR + c]     = kv.x; Ks[r * QSTR + c + 1] = kv.y;
            Ks[r * QSTR + c + 2] = kv.z; Ks[r * QSTR + c + 3] = kv.w;
            float4 vv = *(const float4*)&g_v[boff + (size_t)(k_base + r) * HD + c];
            Vs[r * QSTR + c]     = vv.x; Vs[r * QSTR + c + 1] = vv.y;
            Vs[r * QSTR + c + 2] = vv.z; Vs[r * QSTR + c + 3] = vv.w;
        }
        __syncthreads();

        // S = Q @ K^T  (4x4 per thread, h unrolled by 4 via float4)
        float s[4][4];
#pragma unroll
        for (int i = 0; i < 4; i++)
#pragma unroll
            for (int j = 0; j < 4; j++) s[i][j] = 0.f;

#pragma unroll 4
        for (int h = 0; h < HD; h += 4) {
            float4 q4[4], k4[4];
#pragma unroll
            for (int i = 0; i < 4; i++) q4[i] = *(const float4*)&Qs[(sr0 + i) * QSTR + h];
#pragma unroll
            for (int j = 0; j < 4; j++) k4[j] = *(const float4*)&Ks[(sc0 + j) * QSTR + h];
#pragma unroll
            for (int i = 0; i < 4; i++)
#pragma unroll
                for (int j = 0; j < 4; j++) {
                    s[i][j] = fmaf(q4[i].x, k4[j].x, s[i][j]);
                    s[i][j] = fmaf(q4[i].y, k4[j].y, s[i][j]);
                    s[i][j] = fmaf(q4[i].z, k4[j].z, s[i][j]);
                    s[i][j] = fmaf(q4[i].w, k4[j].w, s[i][j]);
                }
        }

        // scale + causal mask -> Ps
        const bool diag = (kt == qt);
#pragma unroll
        for (int i = 0; i < 4; i++)
#pragma unroll
            for (int j = 0; j < 4; j++) {
                float val = s[i][j] * scale;
                if (diag && (sc0 + j) > (sr0 + i)) val = -1e30f;
                Ps[(sr0 + i) * PSTR + sc0 + j] = val;
            }
        __syncthreads();

        // online softmax: 4 consecutive lanes per row (same warp)
        {
            const int row = tid >> 2;
            const int seg = tid & 3;
            float* prow = &Ps[row * PSTR + seg * 16];
            float mx = -1e30f;
#pragma unroll
            for (int j = 0; j < 16; j++) mx = fmaxf(mx, prow[j]);
            mx = fmaxf(mx, __shfl_xor_sync(0xffffffffu, mx, 1));
            mx = fmaxf(mx, __shfl_xor_sync(0xffffffffu, mx, 2));
            const float m_old = m_s[row];
            const float m_new = fmaxf(m_old, mx);
            float sum = 0.f;
#pragma unroll
            for (int j = 0; j < 16; j++) {
                float p = __expf(prow[j] - m_new);
                prow[j] = p;
                sum += p;
            }
            sum += __shfl_xor_sync(0xffffffffu, sum, 1);
            sum += __shfl_xor_sync(0xffffffffu, sum, 2);
            if (seg == 0) {
                const float corr = __expf(m_old - m_new);
                l_s[row] = l_s[row] * corr + sum;
                m_s[row] = m_new;
                c_s[row] = corr;
            }
        }
        __syncthreads();

        // rescale O, then O += P @ V
#pragma unroll
        for (int i = 0; i < 4; i++) {
            const float corr = c_s[vr0 + i];
#pragma unroll
            for (int j = 0; j < 8; j++) o[i][j] *= corr;
        }

#pragma unroll 4
        for (int k = 0; k < 64; k++) {
            float p[4];
#pragma unroll
            for (int i = 0; i < 4; i++) p[i] = Ps[(vr0 + i) * PSTR + k];
            const float4 v0 = *(const float4*)&Vs[k * QSTR + vh0];
            const float4 v1 = *(const float4*)&Vs[k * QSTR + vh0 + 4];
#pragma unroll
            for (int i = 0; i < 4; i++) {
                o[i][0] = fmaf(p[i], v0.x, o[i][0]);
                o[i][1] = fmaf(p[i], v0.y, o[i][1]);
                o[i][2] = fmaf(p[i], v0.z, o[i][2]);
                o[i][3] = fmaf(p[i], v0.w, o[i][3]);
                o[i][4] = fmaf(p[i], v1.x, o[i][4]);
                o[i][5] = fmaf(p[i], v1.y, o[i][5]);
                o[i][6] = fmaf(p[i], v1.z, o[i][6]);
                o[i][7] = fmaf(p[i], v1.w, o[i][7]);
            }
        }
    }

    // normalize and write
#pragma unroll
    for (int i = 0; i < 4; i++) {
        const float inv = 1.f / l_s[vr0 + i];
#pragma unroll
        for (int j = 0; j < 8; j += 4) {
            float4 r = make_float4(o[i][j] * inv, o[i][j + 1] * inv,
                                   o[i][j + 2] * inv, o[i][j + 3] * inv);
            *(float4*)&out[boff + (size_t)(q_base + vr0 + i) * HD + vh0 + j] = r;
        }
    }
}

// ---------------------------------------------------------------------------
extern "C" void kernel_launch(void* const* d_in, const int* in_sizes, int n_in,
                              void* d_out, int out_size)
{
    const float* x  = (const float*)d_in[0];
    const float* Wq = (const float*)d_in[1];
    const float* Wk = (const float*)d_in[2];
    const float* Wv = (const float*)d_in[3];
    float* out = (float*)d_out;

    cudaFuncSetAttribute(attn_kernel,
                         cudaFuncAttributeMaxDynamicSharedMemorySize,
                         ATTN_SMEM_BYTES);

    // QKV projection: grid (M/64, 3)
    qkv_kernel<<<dim3(MTOT / 64, 3), 256>>>(x, Wq, Wk, Wv);

    // Attention: grid (S/64, B)
    attn_kernel<<<dim3(SEQ / 64, BATCH), 256, ATTN_SMEM_BYTES>>>(out);
}

// round 5
// speedup vs baseline: 4.5174x; 4.5174x over previous
#include <cuda_runtime.h>
#include <math.h>
#include <stdint.h>

#define BATCH 4
#define SEQ   4096
#define EMB   1024
#define HD    128
#define MTOT  (BATCH * SEQ)

// Scratch for projected q, k, v (fp32), allocation-free device globals
__device__ float g_q[(size_t)MTOT * HD];
__device__ float g_k[(size_t)MTOT * HD];
__device__ float g_v[(size_t)MTOT * HD];

// ---------------------------------------------------------------------------
// tf32 helpers
// ---------------------------------------------------------------------------
__device__ __forceinline__ uint32_t f2tf(float f) {
    uint32_t u;
    asm("cvt.rna.tf32.f32 %0, %1;" : "=r"(u) : "f"(f));
    return u;
}

// D += A(16x8, tf32, row) * B(8x8, tf32, col); accumulate in place.
__device__ __forceinline__ void mma8(float* d, const uint32_t* a, const uint32_t* b) {
    asm volatile(
        "mma.sync.aligned.m16n8k8.row.col.f32.tf32.tf32.f32 "
        "{%0,%1,%2,%3}, {%4,%5,%6,%7}, {%8,%9}, {%0,%1,%2,%3};\n"
        : "+f"(d[0]), "+f"(d[1]), "+f"(d[2]), "+f"(d[3])
        : "r"(a[0]), "r"(a[1]), "r"(a[2]), "r"(a[3]), "r"(b[0]), "r"(b[1]));
}

// ---------------------------------------------------------------------------
// Kernel 1: QKV projection, out[which] = x[M,E] @ W[E,H], tf32 MMA.
// CTA tile 128(M) x 128(N=HD), BK=32. 8 warps: warp tile 32x64.
// ---------------------------------------------------------------------------
#define XSTR 36     // 36 % 32 == 4  -> A-frag loads conflict-free
#define WSTR 136    // 136 % 32 == 8 -> B-frag loads conflict-free

__global__ __launch_bounds__(256) void qkv_kernel(
    const float* __restrict__ x,
    const float* __restrict__ Wq,
    const float* __restrict__ Wk,
    const float* __restrict__ Wv)
{
    const int which = blockIdx.y;
    const float* __restrict__ W = (which == 0) ? Wq : (which == 1) ? Wk : Wv;
    float* __restrict__ out = (which == 0) ? g_q : (which == 1) ? g_k : g_v;

    __shared__ uint32_t Xs[128 * XSTR];
    __shared__ uint32_t Ws[32 * WSTR];

    const int tid  = threadIdx.x;
    const int warp = tid >> 5;
    const int lane = tid & 31;
    const int g = lane >> 2;
    const int t = lane & 3;
    const int wm = warp & 3;        // 4 M bands of 32
    const int wn = warp >> 2;       // 2 N halves of 64
    const int m0 = wm * 32;
    const int n0 = wn * 64;
    const int row_base = blockIdx.x * 128;

    float acc[2][8][4];
#pragma unroll
    for (int i = 0; i < 2; i++)
#pragma unroll
        for (int j = 0; j < 8; j++)
#pragma unroll
            for (int r = 0; r < 4; r++) acc[i][j][r] = 0.f;

    for (int k0 = 0; k0 < EMB; k0 += 32) {
        // stage X tile 128x32 (1024 float4, 4/thread)
#pragma unroll
        for (int it = 0; it < 4; it++) {
            int idx = tid + it * 256;
            int r = idx >> 3;
            int c = (idx & 7) * 4;
            float4 v = *(const float4*)&x[(size_t)(row_base + r) * EMB + k0 + c];
            uint4 u = make_uint4(f2tf(v.x), f2tf(v.y), f2tf(v.z), f2tf(v.w));
            *(uint4*)&Xs[r * XSTR + c] = u;
        }
        // stage W tile 32x128 (1024 float4, 4/thread)
#pragma unroll
        for (int it = 0; it < 4; it++) {
            int idx = tid + it * 256;
            int r = idx >> 5;
            int c = (idx & 31) * 4;
            float4 v = *(const float4*)&W[(size_t)(k0 + r) * HD + c];
            uint4 u = make_uint4(f2tf(v.x), f2tf(v.y), f2tf(v.z), f2tf(v.w));
            *(uint4*)&Ws[r * WSTR + c] = u;
        }
        __syncthreads();

#pragma unroll
        for (int ks = 0; ks < 4; ks++) {
            const int kk = ks * 8;
            uint32_t a[2][4];
#pragma unroll
            for (int i = 0; i < 2; i++) {
                int ab = (m0 + i * 16 + g) * XSTR + kk + t;
                a[i][0] = Xs[ab];
                a[i][1] = Xs[ab + 8 * XSTR];
                a[i][2] = Xs[ab + 4];
                a[i][3] = Xs[ab + 8 * XSTR + 4];
            }
#pragma unroll
            for (int j = 0; j < 8; j++) {
                int bb = (kk + t) * WSTR + n0 + j * 8 + g;
                uint32_t b[2] = { Ws[bb], Ws[bb + 4 * WSTR] };
                mma8(acc[0][j], a[0], b);
                mma8(acc[1][j], a[1], b);
            }
        }
        __syncthreads();
    }

#pragma unroll
    for (int i = 0; i < 2; i++)
#pragma unroll
        for (int j = 0; j < 8; j++) {
            int row = row_base + m0 + i * 16 + g;
            int col = n0 + j * 8 + 2 * t;
            *(float2*)&out[(size_t)row * HD + col] =
                make_float2(acc[i][j][0], acc[i][j][1]);
            *(float2*)&out[(size_t)(row + 8) * HD + col] =
                make_float2(acc[i][j][2], acc[i][j][3]);
        }
}

// ---------------------------------------------------------------------------
// Kernel 2: causal flash attention, tf32 MMA.
// BM=64 queries, BN=64 keys per iter. 8 warps: warp w owns m16 tile (w&3),
// n-half (w>>2). Softmax stats in registers + small smem exchange per iter.
// ---------------------------------------------------------------------------
#define QKSTR 132   // 132 % 32 == 4 (A-pattern rows: Q, K)
#define VSTR  136   // 136 % 32 == 8 (B-pattern rows: V)
#define PSTR  68    // 68  % 32 == 4 (A-pattern rows: P)

#define ATTN_SMEM_U32 (2 * 64 * QKSTR + 64 * VSTR + 64 * PSTR + 4 * 64)
#define ATTN_SMEM_BYTES (ATTN_SMEM_U32 * 4)

__global__ __launch_bounds__(256) void attn_kernel(float* __restrict__ out)
{
    const int batch = blockIdx.y;
    const int qt = (int)(gridDim.x - 1) - (int)blockIdx.x;   // heavy tiles first
    const int q_base = qt * 64;
    const size_t boff = (size_t)batch * SEQ * HD;

    extern __shared__ uint32_t sm[];
    uint32_t* Qs = sm;                      // 64 x 132
    uint32_t* Ks = Qs + 64 * QKSTR;         // 64 x 132
    uint32_t* Vs = Ks + 64 * QKSTR;         // 64 x 136
    uint32_t* Ps = Vs + 64 * VSTR;          // 64 x 68
    float* redmax = (float*)(Ps + 64 * PSTR);   // [2][64]
    float* redsum = redmax + 2 * 64;            // [2][64]

    const int tid  = threadIdx.x;
    const int warp = tid >> 5;
    const int lane = tid & 31;
    const int g = lane >> 2;
    const int t = lane & 3;
    const int mt = warp & 3;        // m16 tile index
    const int nh = warp >> 2;       // n / hd half
    const int m0 = mt * 16;
    const int nb = nh * 32;         // key-col base for S
    const int hb = nh * 64;         // hd-col base for O
    const int r0l = m0 + g;         // local rows this thread owns
    const int r1l = m0 + g + 8;

    const float qscale = rsqrtf((float)HD);

    // stage Q (scaled, tf32): 64x128 = 2048 float4, 8 per thread
#pragma unroll
    for (int it = 0; it < 8; it++) {
        int idx = tid + it * 256;
        int r = idx >> 5;
        int c = (idx & 31) * 4;
        float4 v = *(const float4*)&g_q[boff + (size_t)(q_base + r) * HD + c];
        uint4 u = make_uint4(f2tf(v.x * qscale), f2tf(v.y * qscale),
                             f2tf(v.z * qscale), f2tf(v.w * qscale));
        *(uint4*)&Qs[r * QKSTR + c] = u;
    }

    float o[8][4];
#pragma unroll
    for (int j = 0; j < 8; j++)
#pragma unroll
        for (int r = 0; r < 4; r++) o[j][r] = 0.f;

    float m_i0 = -1e30f, m_i1 = -1e30f;
    float l_i0 = 0.f,    l_i1 = 0.f;

    for (int kt = 0; kt <= qt; kt++) {
        __syncthreads();    // prior iter's PV reads / Q staging visible

        // stage K, V tiles (tf32): 2 x 2048 float4, 16 per thread
        const int k_base = kt * 64;
#pragma unroll
        for (int it = 0; it < 8; it++) {
            int idx = tid + it * 256;
            int r = idx >> 5;
            int c = (idx & 31) * 4;
            float4 kv = *(const float4*)&g_k[boff + (size_t)(k_base + r) * HD + c];
            *(uint4*)&Ks[r * QKSTR + c] =
                make_uint4(f2tf(kv.x), f2tf(kv.y), f2tf(kv.z), f2tf(kv.w));
            float4 vv = *(const float4*)&g_v[boff + (size_t)(k_base + r) * HD + c];
            *(uint4*)&Vs[r * VSTR + c] =
                make_uint4(f2tf(vv.x), f2tf(vv.y), f2tf(vv.z), f2tf(vv.w));
        }
        __syncthreads();

        // S = Q @ K^T  (warp: 1 m-tile x 4 n-tiles, k=128)
        float s[4][4];
#pragma unroll
        for (int j = 0; j < 4; j++)
#pragma unroll
            for (int r = 0; r < 4; r++) s[j][r] = 0.f;

#pragma unroll
        for (int ks = 0; ks < 16; ks++) {
            const int kk = ks * 8;
            uint32_t a[4];
            int ab = r0l * QKSTR + kk + t;
            a[0] = Qs[ab];
            a[1] = Qs[ab + 8 * QKSTR];
            a[2] = Qs[ab + 4];
            a[3] = Qs[ab + 8 * QKSTR + 4];
#pragma unroll
            for (int j = 0; j < 4; j++) {
                int bb = (nb + j * 8 + g) * QKSTR + kk + t;
                uint32_t b[2] = { Ks[bb], Ks[bb + 4] };
                mma8(s[j], a, b);
            }
        }

        // causal mask on diagonal tile
        if (kt == qt) {
#pragma unroll
            for (int j = 0; j < 4; j++) {
                int cn = nb + j * 8 + 2 * t;
                if (cn     > r0l) s[j][0] = -1e30f;
                if (cn + 1 > r0l) s[j][1] = -1e30f;
                if (cn     > r1l) s[j][2] = -1e30f;
                if (cn + 1 > r1l) s[j][3] = -1e30f;
            }
        }

        // per-half row max -> smem
        float mx0 = -1e30f, mx1 = -1e30f;
#pragma unroll
        for (int j = 0; j < 4; j++) {
            mx0 = fmaxf(mx0, fmaxf(s[j][0], s[j][1]));
            mx1 = fmaxf(mx1, fmaxf(s[j][2], s[j][3]));
        }
        mx0 = fmaxf(mx0, __shfl_xor_sync(0xffffffffu, mx0, 1));
        mx0 = fmaxf(mx0, __shfl_xor_sync(0xffffffffu, mx0, 2));
        mx1 = fmaxf(mx1, __shfl_xor_sync(0xffffffffu, mx1, 1));
        mx1 = fmaxf(mx1, __shfl_xor_sync(0xffffffffu, mx1, 2));
        if (t == 0) {
            redmax[nh * 64 + r0l] = mx0;
            redmax[nh * 64 + r1l] = mx1;
        }
        __syncthreads();

        const float m_new0 = fmaxf(m_i0, fmaxf(redmax[r0l], redmax[64 + r0l]));
        const float m_new1 = fmaxf(m_i1, fmaxf(redmax[r1l], redmax[64 + r1l]));

        // exp, P -> smem (tf32), per-half row sum -> smem
        float sum0 = 0.f, sum1 = 0.f;
#pragma unroll
        for (int j = 0; j < 4; j++) {
            float p00 = __expf(s[j][0] - m_new0);
            float p01 = __expf(s[j][1] - m_new0);
            float p10 = __expf(s[j][2] - m_new1);
            float p11 = __expf(s[j][3] - m_new1);
            sum0 += p00 + p01;
            sum1 += p10 + p11;
            int cn = nb + j * 8 + 2 * t;
            *(uint2*)&Ps[r0l * PSTR + cn] = make_uint2(f2tf(p00), f2tf(p01));
            *(uint2*)&Ps[r1l * PSTR + cn] = make_uint2(f2tf(p10), f2tf(p11));
        }
        sum0 += __shfl_xor_sync(0xffffffffu, sum0, 1);
        sum0 += __shfl_xor_sync(0xffffffffu, sum0, 2);
        sum1 += __shfl_xor_sync(0xffffffffu, sum1, 1);
        sum1 += __shfl_xor_sync(0xffffffffu, sum1, 2);
        if (t == 0) {
            redsum[nh * 64 + r0l] = sum0;
            redsum[nh * 64 + r1l] = sum1;
        }
        __syncthreads();

        const float corr0 = __expf(m_i0 - m_new0);
        const float corr1 = __expf(m_i1 - m_new1);
        l_i0 = l_i0 * corr0 + redsum[r0l] + redsum[64 + r0l];
        l_i1 = l_i1 * corr1 + redsum[r1l] + redsum[64 + r1l];
        m_i0 = m_new0;
        m_i1 = m_new1;

        // rescale O, then O += P @ V
#pragma unroll
        for (int j = 0; j < 8; j++) {
            o[j][0] *= corr0; o[j][1] *= corr0;
            o[j][2] *= corr1; o[j][3] *= corr1;
        }
#pragma unroll
        for (int ks = 0; ks < 8; ks++) {
            const int kk = ks * 8;
            uint32_t a[4];
            int ab = r0l * PSTR + kk + t;
            a[0] = Ps[ab];
            a[1] = Ps[ab + 8 * PSTR];
            a[2] = Ps[ab + 4];
            a[3] = Ps[ab + 8 * PSTR + 4];
#pragma unroll
            for (int j = 0; j < 8; j++) {
                int bb = (kk + t) * VSTR + hb + j * 8 + g;
                uint32_t b[2] = { Vs[bb], Vs[bb + 4 * VSTR] };
                mma8(o[j], a, b);
            }
        }
    }

    // normalize and write
    const float inv0 = 1.f / l_i0;
    const float inv1 = 1.f / l_i1;
#pragma unroll
    for (int j = 0; j < 8; j++) {
        int col = hb + j * 8 + 2 * t;
        int row = q_base + r0l;
        *(float2*)&out[boff + (size_t)row * HD + col] =
            make_float2(o[j][0] * inv0, o[j][1] * inv0);
        *(float2*)&out[boff + (size_t)(row + 8) * HD + col] =
            make_float2(o[j][2] * inv1, o[j][3] * inv1);
    }
}

// ---------------------------------------------------------------------------
extern "C" void kernel_launch(void* const* d_in, const int* in_sizes, int n_in,
                              void* d_out, int out_size)
{
    const float* x  = (const float*)d_in[0];
    const float* Wq = (const float*)d_in[1];
    const float* Wk = (const float*)d_in[2];
    const float* Wv = (const float*)d_in[3];
    float* out = (float*)d_out;

    cudaFuncSetAttribute(attn_kernel,
                         cudaFuncAttributeMaxDynamicSharedMemorySize,
                         ATTN_SMEM_BYTES);

    qkv_kernel<<<dim3(MTOT / 128, 3), 256>>>(x, Wq, Wk, Wv);
    attn_kernel<<<dim3(SEQ / 64, BATCH), 256, ATTN_SMEM_BYTES>>>(out);
}

// round 6
// speedup vs baseline: 4.5235x; 1.0014x over previous
#include <cuda_runtime.h>
#include <math.h>
#include <stdint.h>

#define BATCH 4
#define SEQ   4096
#define EMB   1024
#define HD    128
#define MTOT  (BATCH * SEQ)

// Scratch for projected q, k, v (fp32), allocation-free device globals
__device__ float g_q[(size_t)MTOT * HD];
__device__ float g_k[(size_t)MTOT * HD];
__device__ float g_v[(size_t)MTOT * HD];

// ---------------------------------------------------------------------------
// tf32 helpers
// ---------------------------------------------------------------------------
__device__ __forceinline__ uint32_t f2tf(float f) {
    uint32_t u;
    asm("cvt.rna.tf32.f32 %0, %1;" : "=r"(u) : "f"(f));
    return u;
}

// D += A(16x8, tf32, row) * B(8x8, tf32, col); accumulate in place.
__device__ __forceinline__ void mma8(float* d, const uint32_t* a, const uint32_t* b) {
    asm volatile(
        "mma.sync.aligned.m16n8k8.row.col.f32.tf32.tf32.f32 "
        "{%0,%1,%2,%3}, {%4,%5,%6,%7}, {%8,%9}, {%0,%1,%2,%3};\n"
        : "+f"(d[0]), "+f"(d[1]), "+f"(d[2]), "+f"(d[3])
        : "r"(a[0]), "r"(a[1]), "r"(a[2]), "r"(a[3]), "r"(b[0]), "r"(b[1]));
}

// ---------------------------------------------------------------------------
// Kernel 1: QKV projection, out[which] = x[M,E] @ W[E,H], tf32 MMA.
// CTA tile 128(M) x 128(N=HD), BK=32. 8 warps: warp tile 32x64.
// ---------------------------------------------------------------------------
#define XSTR 36     // 36 % 32 == 4  -> A-frag loads conflict-free
#define WSTR 136    // 136 % 32 == 8 -> B-frag loads conflict-free

__global__ __launch_bounds__(256) void qkv_kernel(
    const float* __restrict__ x,
    const float* __restrict__ Wq,
    const float* __restrict__ Wk,
    const float* __restrict__ Wv)
{
    const int which = blockIdx.y;
    const float* __restrict__ W = (which == 0) ? Wq : (which == 1) ? Wk : Wv;
    float* __restrict__ out = (which == 0) ? g_q : (which == 1) ? g_k : g_v;

    __shared__ uint32_t Xs[128 * XSTR];
    __shared__ uint32_t Ws[32 * WSTR];

    const int tid  = threadIdx.x;
    const int warp = tid >> 5;
    const int lane = tid & 31;
    const int g = lane >> 2;
    const int t = lane & 3;
    const int wm = warp & 3;        // 4 M bands of 32
    const int wn = warp >> 2;       // 2 N halves of 64
    const int m0 = wm * 32;
    const int n0 = wn * 64;
    const int row_base = blockIdx.x * 128;

    float acc[2][8][4];
#pragma unroll
    for (int i = 0; i < 2; i++)
#pragma unroll
        for (int j = 0; j < 8; j++)
#pragma unroll
            for (int r = 0; r < 4; r++) acc[i][j][r] = 0.f;

    for (int k0 = 0; k0 < EMB; k0 += 32) {
        // stage X tile 128x32 (1024 float4, 4/thread)
#pragma unroll
        for (int it = 0; it < 4; it++) {
            int idx = tid + it * 256;
            int r = idx >> 3;
            int c = (idx & 7) * 4;
            float4 v = *(const float4*)&x[(size_t)(row_base + r) * EMB + k0 + c];
            uint4 u = make_uint4(f2tf(v.x), f2tf(v.y), f2tf(v.z), f2tf(v.w));
            *(uint4*)&Xs[r * XSTR + c] = u;
        }
        // stage W tile 32x128 (1024 float4, 4/thread)
#pragma unroll
        for (int it = 0; it < 4; it++) {
            int idx = tid + it * 256;
            int r = idx >> 5;
            int c = (idx & 31) * 4;
            float4 v = *(const float4*)&W[(size_t)(k0 + r) * HD + c];
            uint4 u = make_uint4(f2tf(v.x), f2tf(v.y), f2tf(v.z), f2tf(v.w));
            *(uint4*)&Ws[r * WSTR + c] = u;
        }
        __syncthreads();

#pragma unroll
        for (int ks = 0; ks < 4; ks++) {
            const int kk = ks * 8;
            uint32_t a[2][4];
#pragma unroll
            for (int i = 0; i < 2; i++) {
                int ab = (m0 + i * 16 + g) * XSTR + kk + t;
                a[i][0] = Xs[ab];
                a[i][1] = Xs[ab + 8 * XSTR];
                a[i][2] = Xs[ab + 4];
                a[i][3] = Xs[ab + 8 * XSTR + 4];
            }
#pragma unroll
            for (int j = 0; j < 8; j++) {
                int bb = (kk + t) * WSTR + n0 + j * 8 + g;
                uint32_t b[2] = { Ws[bb], Ws[bb + 4 * WSTR] };
                mma8(acc[0][j], a[0], b);
                mma8(acc[1][j], a[1], b);
            }
        }
        __syncthreads();
    }

#pragma unroll
    for (int i = 0; i < 2; i++)
#pragma unroll
        for (int j = 0; j < 8; j++) {
            int row = row_base + m0 + i * 16 + g;
            int col = n0 + j * 8 + 2 * t;
            *(float2*)&out[(size_t)row * HD + col] =
                make_float2(acc[i][j][0], acc[i][j][1]);
            *(float2*)&out[(size_t)(row + 8) * HD + col] =
                make_float2(acc[i][j][2], acc[i][j][3]);
        }
}

// ---------------------------------------------------------------------------
// Kernel 2: causal flash attention, tf32 MMA.
// BM=64 queries, BN=64 keys per iter. 8 warps: warp w owns m16 tile (w&3),
// n-half (w>>2). Softmax stats in registers + small smem exchange per iter.
// ---------------------------------------------------------------------------
#define QKSTR 132   // 132 % 32 == 4 (A-pattern rows: Q, K)
#define VSTR  136   // 136 % 32 == 8 (B-pattern rows: V)
#define PSTR  68    // 68  % 32 == 4 (A-pattern rows: P)

#define ATTN_SMEM_U32 (2 * 64 * QKSTR + 64 * VSTR + 64 * PSTR + 4 * 64)
#define ATTN_SMEM_BYTES (ATTN_SMEM_U32 * 4)

__global__ __launch_bounds__(256) void attn_kernel(float* __restrict__ out)
{
    const int batch = blockIdx.y;
    const int qt = (int)(gridDim.x - 1) - (int)blockIdx.x;   // heavy tiles first
    const int q_base = qt * 64;
    const size_t boff = (size_t)batch * SEQ * HD;

    extern __shared__ uint32_t sm[];
    uint32_t* Qs = sm;                      // 64 x 132
    uint32_t* Ks = Qs + 64 * QKSTR;         // 64 x 132
    uint32_t* Vs = Ks + 64 * QKSTR;         // 64 x 136
    uint32_t* Ps = Vs + 64 * VSTR;          // 64 x 68
    float* redmax = (float*)(Ps + 64 * PSTR);   // [2][64]
    float* redsum = redmax + 2 * 64;            // [2][64]

    const int tid  = threadIdx.x;
    const int warp = tid >> 5;
    const int lane = tid & 31;
    const int g = lane >> 2;
    const int t = lane & 3;
    const int mt = warp & 3;        // m16 tile index
    const int nh = warp >> 2;       // n / hd half
    const int m0 = mt * 16;
    const int nb = nh * 32;         // key-col base for S
    const int hb = nh * 64;         // hd-col base for O
    const int r0l = m0 + g;         // local rows this thread owns
    const int r1l = m0 + g + 8;

    const float qscale = rsqrtf((float)HD);

    // stage Q (scaled, tf32): 64x128 = 2048 float4, 8 per thread
#pragma unroll
    for (int it = 0; it < 8; it++) {
        int idx = tid + it * 256;
        int r = idx >> 5;
        int c = (idx & 31) * 4;
        float4 v = *(const float4*)&g_q[boff + (size_t)(q_base + r) * HD + c];
        uint4 u = make_uint4(f2tf(v.x * qscale), f2tf(v.y * qscale),
                             f2tf(v.z * qscale), f2tf(v.w * qscale));
        *(uint4*)&Qs[r * QKSTR + c] = u;
    }

    float o[8][4];
#pragma unroll
    for (int j = 0; j < 8; j++)
#pragma unroll
        for (int r = 0; r < 4; r++) o[j][r] = 0.f;

    float m_i0 = -1e30f, m_i1 = -1e30f;
    float l_i0 = 0.f,    l_i1 = 0.f;

    for (int kt = 0; kt <= qt; kt++) {
        __syncthreads();    // prior iter's PV reads / Q staging visible

        // stage K, V tiles (tf32): 2 x 2048 float4, 16 per thread
        const int k_base = kt * 64;
#pragma unroll
        for (int it = 0; it < 8; it++) {
            int idx = tid + it * 256;
            int r = idx >> 5;
            int c = (idx & 31) * 4;
            float4 kv = *(const float4*)&g_k[boff + (size_t)(k_base + r) * HD + c];
            *(uint4*)&Ks[r * QKSTR + c] =
                make_uint4(f2tf(kv.x), f2tf(kv.y), f2tf(kv.z), f2tf(kv.w));
            float4 vv = *(const float4*)&g_v[boff + (size_t)(k_base + r) * HD + c];
            *(uint4*)&Vs[r * VSTR + c] =
                make_uint4(f2tf(vv.x), f2tf(vv.y), f2tf(vv.z), f2tf(vv.w));
        }
        __syncthreads();

        // S = Q @ K^T  (warp: 1 m-tile x 4 n-tiles, k=128)
        float s[4][4];
#pragma unroll
        for (int j = 0; j < 4; j++)
#pragma unroll
            for (int r = 0; r < 4; r++) s[j][r] = 0.f;

#pragma unroll
        for (int ks = 0; ks < 16; ks++) {
            const int kk = ks * 8;
            uint32_t a[4];
            int ab = r0l * QKSTR + kk + t;
            a[0] = Qs[ab];
            a[1] = Qs[ab + 8 * QKSTR];
            a[2] = Qs[ab + 4];
            a[3] = Qs[ab + 8 * QKSTR + 4];
#pragma unroll
            for (int j = 0; j < 4; j++) {
                int bb = (nb + j * 8 + g) * QKSTR + kk + t;
                uint32_t b[2] = { Ks[bb], Ks[bb + 4] };
                mma8(s[j], a, b);
            }
        }

        // causal mask on diagonal tile
        if (kt == qt) {
#pragma unroll
            for (int j = 0; j < 4; j++) {
                int cn = nb + j * 8 + 2 * t;
                if (cn     > r0l) s[j][0] = -1e30f;
                if (cn + 1 > r0l) s[j][1] = -1e30f;
                if (cn     > r1l) s[j][2] = -1e30f;
                if (cn + 1 > r1l) s[j][3] = -1e30f;
            }
        }

        // per-half row max -> smem
        float mx0 = -1e30f, mx1 = -1e30f;
#pragma unroll
        for (int j = 0; j < 4; j++) {
            mx0 = fmaxf(mx0, fmaxf(s[j][0], s[j][1]));
            mx1 = fmaxf(mx1, fmaxf(s[j][2], s[j][3]));
        }
        mx0 = fmaxf(mx0, __shfl_xor_sync(0xffffffffu, mx0, 1));
        mx0 = fmaxf(mx0, __shfl_xor_sync(0xffffffffu, mx0, 2));
        mx1 = fmaxf(mx1, __shfl_xor_sync(0xffffffffu, mx1, 1));
        mx1 = fmaxf(mx1, __shfl_xor_sync(0xffffffffu, mx1, 2));
        if (t == 0) {
            redmax[nh * 64 + r0l] = mx0;
            redmax[nh * 64 + r1l] = mx1;
        }
        __syncthreads();

        const float m_new0 = fmaxf(m_i0, fmaxf(redmax[r0l], redmax[64 + r0l]));
        const float m_new1 = fmaxf(m_i1, fmaxf(redmax[r1l], redmax[64 + r1l]));

        // exp, P -> smem (tf32), per-half row sum -> smem
        float sum0 = 0.f, sum1 = 0.f;
#pragma unroll
        for (int j = 0; j < 4; j++) {
            float p00 = __expf(s[j][0] - m_new0);
            float p01 = __expf(s[j][1] - m_new0);
            float p10 = __expf(s[j][2] - m_new1);
            float p11 = __expf(s[j][3] - m_new1);
            sum0 += p00 + p01;
            sum1 += p10 + p11;
            int cn = nb + j * 8 + 2 * t;
            *(uint2*)&Ps[r0l * PSTR + cn] = make_uint2(f2tf(p00), f2tf(p01));
            *(uint2*)&Ps[r1l * PSTR + cn] = make_uint2(f2tf(p10), f2tf(p11));
        }
        sum0 += __shfl_xor_sync(0xffffffffu, sum0, 1);
        sum0 += __shfl_xor_sync(0xffffffffu, sum0, 2);
        sum1 += __shfl_xor_sync(0xffffffffu, sum1, 1);
        sum1 += __shfl_xor_sync(0xffffffffu, sum1, 2);
        if (t == 0) {
            redsum[nh * 64 + r0l] = sum0;
            redsum[nh * 64 + r1l] = sum1;
        }
        __syncthreads();

        const float corr0 = __expf(m_i0 - m_new0);
        const float corr1 = __expf(m_i1 - m_new1);
        l_i0 = l_i0 * corr0 + redsum[r0l] + redsum[64 + r0l];
        l_i1 = l_i1 * corr1 + redsum[r1l] + redsum[64 + r1l];
        m_i0 = m_new0;
        m_i1 = m_new1;

        // rescale O, then O += P @ V
#pragma unroll
        for (int j = 0; j < 8; j++) {
            o[j][0] *= corr0; o[j][1] *= corr0;
            o[j][2] *= corr1; o[j][3] *= corr1;
        }
#pragma unroll
        for (int ks = 0; ks < 8; ks++) {
            const int kk = ks * 8;
            uint32_t a[4];
            int ab = r0l * PSTR + kk + t;
            a[0] = Ps[ab];
            a[1] = Ps[ab + 8 * PSTR];
            a[2] = Ps[ab + 4];
            a[3] = Ps[ab + 8 * PSTR + 4];
#pragma unroll
            for (int j = 0; j < 8; j++) {
                int bb = (kk + t) * VSTR + hb + j * 8 + g;
                uint32_t b[2] = { Vs[bb], Vs[bb + 4 * VSTR] };
                mma8(o[j], a, b);
            }
        }
    }

    // normalize and write
    const float inv0 = 1.f / l_i0;
    const float inv1 = 1.f / l_i1;
#pragma unroll
    for (int j = 0; j < 8; j++) {
        int col = hb + j * 8 + 2 * t;
        int row = q_base + r0l;
        *(float2*)&out[boff + (size_t)row * HD + col] =
            make_float2(o[j][0] * inv0, o[j][1] * inv0);
        *(float2*)&out[boff + (size_t)(row + 8) * HD + col] =
            make_float2(o[j][2] * inv1, o[j][3] * inv1);
    }
}

// ---------------------------------------------------------------------------
extern "C" void kernel_launch(void* const* d_in, const int* in_sizes, int n_in,
                              void* d_out, int out_size)
{
    const float* x  = (const float*)d_in[0];
    const float* Wq = (const float*)d_in[1];
    const float* Wk = (const float*)d_in[2];
    const float* Wv = (const float*)d_in[3];
    float* out = (float*)d_out;

    cudaFuncSetAttribute(attn_kernel,
                         cudaFuncAttributeMaxDynamicSharedMemorySize,
                         ATTN_SMEM_BYTES);

    qkv_kernel<<<dim3(MTOT / 128, 3), 256>>>(x, Wq, Wk, Wv);
    attn_kernel<<<dim3(SEQ / 64, BATCH), 256, ATTN_SMEM_BYTES>>>(out);
}